// round 2
// baseline (speedup 1.0000x reference)
#include <cuda_runtime.h>
#include <math.h>

#define HIDDEN   1024
#define THREADS  256          // HIDDEN/4 floats per thread
#define SEQ      2048
#define NUM_FEATS 94
#define PROJ     256
#define NUM_TOKEN_ID 5
#define LN_EPS   1e-12f

// Block-wide (sum, sumsq) reduction over the 1024 values (4 per thread).
// Returns mean and inv_std via references. Must be called by ALL threads.
__device__ __forceinline__ void ln_stats(float4 v, float2* red,
                                         float& mean, float& inv) {
    float s  = v.x + v.y + v.z + v.w;
    float sq = v.x * v.x + v.y * v.y + v.z * v.z + v.w * v.w;
    #pragma unroll
    for (int o = 16; o > 0; o >>= 1) {
        s  += __shfl_down_sync(0xffffffffu, s,  o);
        sq += __shfl_down_sync(0xffffffffu, sq, o);
    }
    int lane = threadIdx.x & 31;
    int warp = threadIdx.x >> 5;
    __syncthreads();                       // protect red[] from previous use
    if (lane == 0) red[warp] = make_float2(s, sq);
    __syncthreads();
    if (warp == 0) {
        float2 r = (lane < 8) ? red[lane] : make_float2(0.f, 0.f);
        s = r.x; sq = r.y;
        #pragma unroll
        for (int o = 4; o > 0; o >>= 1) {
            s  += __shfl_down_sync(0xffffffffu, s,  o);
            sq += __shfl_down_sync(0xffffffffu, sq, o);
        }
        if (lane == 0) red[0] = make_float2(s, sq);
    }
    __syncthreads();
    float2 tot = red[0];
    mean = tot.x * (1.0f / 1024.0f);
    float var = tot.y * (1.0f / 1024.0f) - mean * mean;
    inv = rsqrtf(var + LN_EPS);
}

__global__ __launch_bounds__(THREADS)
void blackhole_embed_kernel(const int*   __restrict__ ids,
                            const float* __restrict__ vals,
                            const int*   __restrict__ fmts,
                            const float* __restrict__ Wword,
                            const float* __restrict__ Wpos,
                            const float* __restrict__ Wtype,
                            const float* __restrict__ ln_g,
                            const float* __restrict__ ln_b,
                            const float* __restrict__ pw1,
                            const float* __restrict__ pb1,
                            const float* __restrict__ pw2,
                            const float* __restrict__ pb2,
                            const float* __restrict__ pln_g,
                            const float* __restrict__ pln_b,
                            float*       __restrict__ out)
{
    const int t   = blockIdx.x;            // token index in [0, B*S)
    const int s   = t & (SEQ - 1);         // position within sequence
    const int tid = threadIdx.x;

    __shared__ float feats[NUM_FEATS + 2];
    __shared__ float h[PROJ];
    __shared__ float2 red[8];

    const int   id  = ids[t];
    const float val = vals[t];
    const bool active = (id == NUM_TOKEN_ID) && !isnan(val);

    // ---- text embedding: word + pos + type(0), vectorized float4 ----
    const float4 w  = reinterpret_cast<const float4*>(Wword + (size_t)id * HIDDEN)[tid];
    const float4 p  = reinterpret_cast<const float4*>(Wpos  + (size_t)s  * HIDDEN)[tid];
    const float4 ty = reinterpret_cast<const float4*>(Wtype)[tid];
    float4 x;
    x.x = w.x + p.x + ty.x;
    x.y = w.y + p.y + ty.y;
    x.z = w.z + p.z + ty.z;
    x.w = w.w + p.w + ty.w;

    if (active) {                          // uniform per-block branch (rare)
        const int fmt = fmts[t];
        // ---- build 94 numeric features (match jax float64 semantics) ----
        if (tid < NUM_FEATS) {
            const double v  = (double)val;
            const double av = fabs(v);
            const double fl = floor(av);
            float f = 0.0f;
            if (tid < 64) {
                // (bits & (1<<i)) > 0 with SIGNED int64: bit 63 is never "> 0"
                const long long bits = __double_as_longlong(v);
                f = (tid < 63 && ((bits >> tid) & 1LL)) ? 1.0f : 0.0f;
            } else if (tid < 74) {
                int units = (int)fmin(fmax(fmod(fl, 10.0), 0.0), 9.0);
                f = ((tid - 64) == units) ? 1.0f : 0.0f;
            } else if (tid < 84) {
                int tens = (int)fmin(fmax(fmod(floor(fl / 10.0), 10.0), 0.0), 9.0);
                f = ((tid - 74) == tens) ? 1.0f : 0.0f;
            } else {
                switch (tid - 84) {
                    case 0: f = (float)log(av + 1e-6); break;
                    case 1: f = (v > 0.0) ? 1.0f : ((v < 0.0) ? -1.0f : 0.0f); break;
                    case 2: f = (av > 1e-6) ? (float)floor(log10(fmax(av, 1e-300))) : 0.0f; break;
                    case 3: f = (av == fl) ? 1.0f : 0.0f; break;
                    case 4: f = (v > 0.0) ? 1.0f : 0.0f; break;
                    case 5: f = (v == 0.0) ? 1.0f : 0.0f; break;
                    case 6: f = (v < 0.0) ? 1.0f : 0.0f; break;
                    case 7: {
                        bool pos_int = (v == floor(v)) && (v > 0.0);
                        double l2 = log2(fmax(v, 1.0));
                        f = (pos_int && (l2 == floor(l2))) ? 1.0f : 0.0f;
                    } break;
                    case 8: f = (fmt == 0) ? 1.0f : 0.0f; break;
                    case 9: f = (fmt == 1) ? 1.0f : 0.0f; break;
                }
            }
            feats[tid] = f;
        }
        __syncthreads();

        // ---- layer 1: [94] @ [94,256] + b1, exact GELU ----
        {
            float acc = pb1[tid];
            #pragma unroll 2
            for (int k = 0; k < NUM_FEATS; k++)
                acc = fmaf(feats[k], pw1[k * PROJ + tid], acc);
            // exact gelu: 0.5*x*(1+erf(x/sqrt(2)))
            h[tid] = 0.5f * acc * (1.0f + erff(acc * 0.70710678118654752f));
        }
        __syncthreads();

        // ---- layer 2: [256] @ [256,1024] + b2 (4 outputs/thread) ----
        float4 acc = reinterpret_cast<const float4*>(pb2)[tid];
        for (int k = 0; k < PROJ; k++) {
            const float hk = h[k];
            const float4 wv = reinterpret_cast<const float4*>(pw2 + (size_t)k * HIDDEN)[tid];
            acc.x = fmaf(hk, wv.x, acc.x);
            acc.y = fmaf(hk, wv.y, acc.y);
            acc.z = fmaf(hk, wv.z, acc.z);
            acc.w = fmaf(hk, wv.w, acc.w);
        }

        // ---- projection LayerNorm ----
        float mean, inv;
        ln_stats(acc, red, mean, inv);
        const float4 g = reinterpret_cast<const float4*>(pln_g)[tid];
        const float4 b = reinterpret_cast<const float4*>(pln_b)[tid];
        x.x += (acc.x - mean) * inv * g.x + b.x;
        x.y += (acc.y - mean) * inv * g.y + b.y;
        x.z += (acc.z - mean) * inv * g.z + b.z;
        x.w += (acc.w - mean) * inv * g.w + b.w;
    }

    // ---- final LayerNorm over (text + num_emb) ----
    float mean, inv;
    ln_stats(x, red, mean, inv);
    const float4 g = reinterpret_cast<const float4*>(ln_g)[tid];
    const float4 b = reinterpret_cast<const float4*>(ln_b)[tid];
    float4 o;
    o.x = (x.x - mean) * inv * g.x + b.x;
    o.y = (x.y - mean) * inv * g.y + b.y;
    o.z = (x.z - mean) * inv * g.z + b.z;
    o.w = (x.w - mean) * inv * g.w + b.w;
    reinterpret_cast<float4*>(out + (size_t)t * HIDDEN)[tid] = o;
}

extern "C" void kernel_launch(void* const* d_in, const int* in_sizes, int n_in,
                              void* d_out, int out_size)
{
    const int*   ids   = (const int*)  d_in[0];   // input_ids [8,2048] (int32 in harness)
    const float* vals  = (const float*)d_in[1];   // numeric_values f32
    const int*   fmts  = (const int*)  d_in[2];   // numeric_formats (int32 in harness)
    const float* Wword = (const float*)d_in[3];   // [50257,1024]
    const float* Wpos  = (const float*)d_in[4];   // [4096,1024]
    const float* Wtype = (const float*)d_in[5];   // [2,1024]
    const float* ln_g  = (const float*)d_in[6];
    const float* ln_b  = (const float*)d_in[7];
    const float* pw1   = (const float*)d_in[8];   // [94,256]
    const float* pb1   = (const float*)d_in[9];
    const float* pw2   = (const float*)d_in[10];  // [256,1024]
    const float* pb2   = (const float*)d_in[11];
    const float* plng  = (const float*)d_in[12];
    const float* plnb  = (const float*)d_in[13];
    float*       out   = (float*)d_out;

    const int n_tokens = in_sizes[0];             // B*S = 16384
    blackhole_embed_kernel<<<n_tokens, THREADS>>>(
        ids, vals, fmts, Wword, Wpos, Wtype, ln_g, ln_b,
        pw1, pb1, pw2, pb2, plng, plnb, out);
}

// round 3
// speedup vs baseline: 1.1846x; 1.1846x over previous
#include <cuda_runtime.h>
#include <math.h>

#define HIDDEN   1024
#define WPB      4                    // warps (tokens) per block
#define THREADS  (WPB * 32)
#define SEQ      2048
#define NUM_FEATS 94
#define PROJ     256
#define NUM_TOKEN_ID 5
#define LN_EPS   1e-12f

// Warp-wide {sum, sumsq} butterfly reduction; every lane gets the totals.
__device__ __forceinline__ void warp_red2(float& s, float& sq) {
    #pragma unroll
    for (int o = 16; o > 0; o >>= 1) {
        s  += __shfl_xor_sync(0xffffffffu, s,  o);
        sq += __shfl_xor_sync(0xffffffffu, sq, o);
    }
}

__global__ __launch_bounds__(THREADS)
void blackhole_embed_kernel(const int*   __restrict__ ids,
                            const float* __restrict__ vals,
                            const int*   __restrict__ fmts,
                            const float* __restrict__ Wword,
                            const float* __restrict__ Wpos,
                            const float* __restrict__ Wtype,
                            const float* __restrict__ ln_g,
                            const float* __restrict__ ln_b,
                            const float* __restrict__ pw1,
                            const float* __restrict__ pb1,
                            const float* __restrict__ pw2,
                            const float* __restrict__ pb2,
                            const float* __restrict__ pln_g,
                            const float* __restrict__ pln_b,
                            float*       __restrict__ out,
                            int          n_tokens)
{
    const int warp = threadIdx.x >> 5;
    const int lane = threadIdx.x & 31;
    const int t    = blockIdx.x * WPB + warp;    // token index
    if (t >= n_tokens) return;                   // safe: no block-wide barriers used
    const int s    = t & (SEQ - 1);              // position within sequence

    // Per-warp scratch for the (astronomically rare) numeric-MLP path.
    __shared__ float feats_sm[WPB][NUM_FEATS + 2];
    __shared__ float h_sm[WPB][PROJ];
    __shared__ float num_sm[WPB][HIDDEN];

    const int   id  = ids[t];
    const float val = vals[t];
    const bool active = (id == NUM_TOKEN_ID) && !isnan(val);

    const float4* Ww = reinterpret_cast<const float4*>(Wword) + (size_t)id * (HIDDEN / 4);
    const float4* Wp = reinterpret_cast<const float4*>(Wpos)  + (size_t)s  * (HIDDEN / 4);
    const float4* Wt = reinterpret_cast<const float4*>(Wtype);

    // ---- text embedding: 8 independent float4 loads per tensor (deep MLP) ----
    float4 x[8];
    #pragma unroll
    for (int j = 0; j < 8; j++) x[j] = Ww[j * 32 + lane];
    #pragma unroll
    for (int j = 0; j < 8; j++) {
        float4 p = Wp[j * 32 + lane];
        x[j].x += p.x; x[j].y += p.y; x[j].z += p.z; x[j].w += p.w;
    }
    #pragma unroll
    for (int j = 0; j < 8; j++) {
        float4 p = Wt[j * 32 + lane];
        x[j].x += p.x; x[j].y += p.y; x[j].z += p.z; x[j].w += p.w;
    }

    if (active) {                               // warp-uniform rare branch
        const int fmt = fmts[t];
        // ---- 94 numeric features (exact float64 semantics of the reference) ----
        float* F = feats_sm[warp];
        const double v  = (double)val;
        const double av = fabs(v);
        const double fl = floor(av);
        for (int i = lane; i < NUM_FEATS; i += 32) {
            float f = 0.0f;
            if (i < 64) {
                // signed int64 mask: (bits & (1<<63)) > 0 is always false
                const long long bits = __double_as_longlong(v);
                f = (i < 63 && ((bits >> i) & 1LL)) ? 1.0f : 0.0f;
            } else if (i < 74) {
                int units = (int)fmin(fmax(fmod(fl, 10.0), 0.0), 9.0);
                f = ((i - 64) == units) ? 1.0f : 0.0f;
            } else if (i < 84) {
                int tens = (int)fmin(fmax(fmod(floor(fl / 10.0), 10.0), 0.0), 9.0);
                f = ((i - 74) == tens) ? 1.0f : 0.0f;
            } else {
                switch (i - 84) {
                    case 0: f = (float)log(av + 1e-6); break;
                    case 1: f = (v > 0.0) ? 1.0f : ((v < 0.0) ? -1.0f : 0.0f); break;
                    case 2: f = (av > 1e-6) ? (float)floor(log10(fmax(av, 1e-300))) : 0.0f; break;
                    case 3: f = (av == fl) ? 1.0f : 0.0f; break;
                    case 4: f = (v > 0.0) ? 1.0f : 0.0f; break;
                    case 5: f = (v == 0.0) ? 1.0f : 0.0f; break;
                    case 6: f = (v < 0.0) ? 1.0f : 0.0f; break;
                    case 7: {
                        bool pos_int = (v == floor(v)) && (v > 0.0);
                        double l2 = log2(fmax(v, 1.0));
                        f = (pos_int && (l2 == floor(l2))) ? 1.0f : 0.0f;
                    } break;
                    case 8: f = (fmt == 0) ? 1.0f : 0.0f; break;
                    case 9: f = (fmt == 1) ? 1.0f : 0.0f; break;
                }
            }
            F[i] = f;
        }
        __syncwarp();

        // ---- layer 1: [94] -> [256], exact GELU (8 cols per lane) ----
        float* H = h_sm[warp];
        #pragma unroll 1
        for (int j = 0; j < 8; j++) {
            const int col = j * 32 + lane;
            float acc = pb1[col];
            for (int k = 0; k < NUM_FEATS; k++)
                acc = fmaf(F[k], pw1[k * PROJ + col], acc);
            H[col] = 0.5f * acc * (1.0f + erff(acc * 0.70710678118654752f));
        }
        __syncwarp();

        // ---- layer 2: [256] -> [1024], staged via smem to limit regs ----
        float* NB = num_sm[warp];
        float sum = 0.f, sq = 0.f;
        #pragma unroll 1
        for (int j = 0; j < 8; j++) {
            float4 acc = reinterpret_cast<const float4*>(pb2)[j * 32 + lane];
            for (int k = 0; k < PROJ; k++) {
                const float hk = H[k];
                const float4 wv =
                    reinterpret_cast<const float4*>(pw2 + (size_t)k * HIDDEN)[j * 32 + lane];
                acc.x = fmaf(hk, wv.x, acc.x);
                acc.y = fmaf(hk, wv.y, acc.y);
                acc.z = fmaf(hk, wv.z, acc.z);
                acc.w = fmaf(hk, wv.w, acc.w);
            }
            reinterpret_cast<float4*>(NB)[j * 32 + lane] = acc;
            sum += acc.x + acc.y + acc.z + acc.w;
            sq  += acc.x * acc.x + acc.y * acc.y + acc.z * acc.z + acc.w * acc.w;
        }

        // ---- projection LayerNorm (warp-only reduction) ----
        warp_red2(sum, sq);
        const float mean = sum * (1.0f / 1024.0f);
        const float inv  = rsqrtf(sq * (1.0f / 1024.0f) - mean * mean + LN_EPS);
        #pragma unroll 1
        for (int j = 0; j < 8; j++) {
            const float4 a = reinterpret_cast<const float4*>(NB)[j * 32 + lane];
            const float4 g = reinterpret_cast<const float4*>(pln_g)[j * 32 + lane];
            const float4 b = reinterpret_cast<const float4*>(pln_b)[j * 32 + lane];
            x[j].x += (a.x - mean) * inv * g.x + b.x;
            x[j].y += (a.y - mean) * inv * g.y + b.y;
            x[j].z += (a.z - mean) * inv * g.z + b.z;
            x[j].w += (a.w - mean) * inv * g.w + b.w;
        }
    }

    // ---- final LayerNorm (warp-only reduction, no barriers) ----
    float sum = 0.f, sq = 0.f;
    #pragma unroll
    for (int j = 0; j < 8; j++) {
        sum += x[j].x + x[j].y + x[j].z + x[j].w;
        sq  += x[j].x * x[j].x + x[j].y * x[j].y + x[j].z * x[j].z + x[j].w * x[j].w;
    }
    warp_red2(sum, sq);
    const float mean = sum * (1.0f / 1024.0f);
    const float inv  = rsqrtf(sq * (1.0f / 1024.0f) - mean * mean + LN_EPS);

    float4* orow = reinterpret_cast<float4*>(out + (size_t)t * HIDDEN);
    #pragma unroll
    for (int j = 0; j < 8; j++) {
        const float4 g = reinterpret_cast<const float4*>(ln_g)[j * 32 + lane];
        const float4 b = reinterpret_cast<const float4*>(ln_b)[j * 32 + lane];
        float4 o;
        o.x = (x[j].x - mean) * inv * g.x + b.x;
        o.y = (x[j].y - mean) * inv * g.y + b.y;
        o.z = (x[j].z - mean) * inv * g.z + b.z;
        o.w = (x[j].w - mean) * inv * g.w + b.w;
        __stcs(orow + j * 32 + lane, o);   // write-once output: evict-first
    }
}

extern "C" void kernel_launch(void* const* d_in, const int* in_sizes, int n_in,
                              void* d_out, int out_size)
{
    const int*   ids   = (const int*)  d_in[0];   // input_ids (int32 in harness)
    const float* vals  = (const float*)d_in[1];
    const int*   fmts  = (const int*)  d_in[2];
    const float* Wword = (const float*)d_in[3];   // [50257,1024]
    const float* Wpos  = (const float*)d_in[4];   // [4096,1024]
    const float* Wtype = (const float*)d_in[5];   // [2,1024]
    const float* ln_g  = (const float*)d_in[6];
    const float* ln_b  = (const float*)d_in[7];
    const float* pw1   = (const float*)d_in[8];   // [94,256]
    const float* pb1   = (const float*)d_in[9];
    const float* pw2   = (const float*)d_in[10];  // [256,1024]
    const float* pb2   = (const float*)d_in[11];
    const float* plng  = (const float*)d_in[12];
    const float* plnb  = (const float*)d_in[13];
    float*       out   = (float*)d_out;

    const int n_tokens = in_sizes[0];             // B*S = 16384
    const int grid = (n_tokens + WPB - 1) / WPB;  // 4096 blocks
    blackhole_embed_kernel<<<grid, THREADS>>>(
        ids, vals, fmts, Wword, Wpos, Wtype, ln_g, ln_b,
        pw1, pb1, pw2, pb2, plng, plnb, out, n_tokens);
}

// round 4
// speedup vs baseline: 1.3509x; 1.1404x over previous
#include <cuda_runtime.h>
#include <math.h>

#define HIDDEN   1024
#define WPB      4                    // warps (tokens) per block in kernel A
#define THREADS_A (WPB * 32)
#define THREADS_B 256
#define SEQ      2048
#define NUM_FEATS 94
#define PROJ     256
#define NUM_TOKEN_ID 5
#define LN_EPS   1e-12f

// Warp-wide {sum, sumsq} butterfly reduction; every lane gets the totals.
__device__ __forceinline__ void warp_red2(float& s, float& sq) {
    #pragma unroll
    for (int o = 16; o > 0; o >>= 1) {
        s  += __shfl_xor_sync(0xffffffffu, s,  o);
        sq += __shfl_xor_sync(0xffffffffu, sq, o);
    }
}

// ===========================================================================
// Kernel A — hot path. Warp-per-token: word + pos + type, final LayerNorm.
// Numeric tokens (id==NUM_TOKEN_ID) get the WRONG value here (num_emb treated
// as 0); kernel B overwrites those rows afterwards.
// ===========================================================================
__global__ __launch_bounds__(THREADS_A, 10)
void embed_main_kernel(const int*   __restrict__ ids,
                       const float* __restrict__ Wword,
                       const float* __restrict__ Wpos,
                       const float* __restrict__ Wtype,
                       const float* __restrict__ ln_g,
                       const float* __restrict__ ln_b,
                       float*       __restrict__ out,
                       int          n_tokens)
{
    const int warp = threadIdx.x >> 5;
    const int lane = threadIdx.x & 31;
    const int t    = blockIdx.x * WPB + warp;
    if (t >= n_tokens) return;
    const int s    = t & (SEQ - 1);

    const int id = ids[t];

    const float4* Ww = reinterpret_cast<const float4*>(Wword) + (size_t)id * (HIDDEN / 4);
    const float4* Wp = reinterpret_cast<const float4*>(Wpos)  + (size_t)s  * (HIDDEN / 4);
    const float4* Wt = reinterpret_cast<const float4*>(Wtype);

    // 8 independent gathers first (deep MLP to the DRAM tier), then add the
    // L2/L1-resident pos/type rows.
    float4 x[8];
    #pragma unroll
    for (int j = 0; j < 8; j++) x[j] = Ww[j * 32 + lane];
    #pragma unroll
    for (int j = 0; j < 8; j++) {
        float4 p = Wp[j * 32 + lane];
        float4 q = Wt[j * 32 + lane];
        x[j].x += p.x + q.x;
        x[j].y += p.y + q.y;
        x[j].z += p.z + q.z;
        x[j].w += p.w + q.w;
    }

    float sum = 0.f, sq = 0.f;
    #pragma unroll
    for (int j = 0; j < 8; j++) {
        sum += x[j].x + x[j].y + x[j].z + x[j].w;
        sq  += x[j].x * x[j].x + x[j].y * x[j].y + x[j].z * x[j].z + x[j].w * x[j].w;
    }
    warp_red2(sum, sq);
    const float mean = sum * (1.0f / 1024.0f);
    const float inv  = rsqrtf(sq * (1.0f / 1024.0f) - mean * mean + LN_EPS);

    float4* orow = reinterpret_cast<float4*>(out + (size_t)t * HIDDEN);
    #pragma unroll
    for (int j = 0; j < 8; j++) {
        const float4 g = reinterpret_cast<const float4*>(ln_g)[j * 32 + lane];
        const float4 b = reinterpret_cast<const float4*>(ln_b)[j * 32 + lane];
        float4 o;
        o.x = (x[j].x - mean) * inv * g.x + b.x;
        o.y = (x[j].y - mean) * inv * g.y + b.y;
        o.z = (x[j].z - mean) * inv * g.z + b.z;
        o.w = (x[j].w - mean) * inv * g.w + b.w;
        __stcs(orow + j * 32 + lane, o);     // write-once: evict-first
    }
}

// ===========================================================================
// Kernel B — fixup for active numeric tokens (expected ~0-2 per batch).
// Each warp scans 32 tokens; for every active one it recomputes the FULL row
// (text embed + 94-feat MLP + projection LN + final LN) and overwrites out.
// ===========================================================================
__global__ __launch_bounds__(THREADS_B)
void embed_fixup_kernel(const int*   __restrict__ ids,
                        const float* __restrict__ vals,
                        const int*   __restrict__ fmts,
                        const float* __restrict__ Wword,
                        const float* __restrict__ Wpos,
                        const float* __restrict__ Wtype,
                        const float* __restrict__ ln_g,
                        const float* __restrict__ ln_b,
                        const float* __restrict__ pw1,
                        const float* __restrict__ pb1,
                        const float* __restrict__ pw2,
                        const float* __restrict__ pb2,
                        const float* __restrict__ pln_g,
                        const float* __restrict__ pln_b,
                        float*       __restrict__ out,
                        int          n_tokens)
{
    const int warp = threadIdx.x >> 5;
    const int lane = threadIdx.x & 31;
    const int tbase = blockIdx.x * THREADS_B + warp * 32;   // warp's token range

    __shared__ float feats_sm[THREADS_B / 32][NUM_FEATS + 2];
    __shared__ float h_sm[THREADS_B / 32][PROJ];

    const int t_lane = tbase + lane;
    bool act = false;
    if (t_lane < n_tokens) {
        act = (ids[t_lane] == NUM_TOKEN_ID) && !isnan(vals[t_lane]);
    }
    unsigned m = __ballot_sync(0xffffffffu, act);

    while (m) {
        const int src = __ffs(m) - 1;
        m &= m - 1;
        const int t = tbase + src;
        const int s = t & (SEQ - 1);
        const float val = __shfl_sync(0xffffffffu, vals ? vals[t_lane < n_tokens ? t_lane : 0] : 0.f, src);
        // (simpler + safe: reload directly)
        const float v32 = vals[t];
        const int   fmt = fmts[t];

        // ---- text embedding ----
        const float4* Ww = reinterpret_cast<const float4*>(Wword) + (size_t)NUM_TOKEN_ID * (HIDDEN / 4);
        const float4* Wp = reinterpret_cast<const float4*>(Wpos)  + (size_t)s * (HIDDEN / 4);
        const float4* Wt = reinterpret_cast<const float4*>(Wtype);
        float4 x[8];
        #pragma unroll
        for (int j = 0; j < 8; j++) {
            float4 w = Ww[j * 32 + lane];
            float4 p = Wp[j * 32 + lane];
            float4 q = Wt[j * 32 + lane];
            x[j].x = w.x + p.x + q.x;
            x[j].y = w.y + p.y + q.y;
            x[j].z = w.z + p.z + q.z;
            x[j].w = w.w + p.w + q.w;
        }

        // ---- 94 numeric features (exact float64 semantics of the reference) ----
        float* F = feats_sm[warp];
        {
            const double v  = (double)v32;
            const double av = fabs(v);
            const double fl = floor(av);
            for (int i = lane; i < NUM_FEATS; i += 32) {
                float f = 0.0f;
                if (i < 64) {
                    // signed int64 mask: (bits & (1<<63)) > 0 is always false
                    const long long bits = __double_as_longlong(v);
                    f = (i < 63 && ((bits >> i) & 1LL)) ? 1.0f : 0.0f;
                } else if (i < 74) {
                    int units = (int)fmin(fmax(fmod(fl, 10.0), 0.0), 9.0);
                    f = ((i - 64) == units) ? 1.0f : 0.0f;
                } else if (i < 84) {
                    int tens = (int)fmin(fmax(fmod(floor(fl / 10.0), 10.0), 0.0), 9.0);
                    f = ((i - 74) == tens) ? 1.0f : 0.0f;
                } else {
                    switch (i - 84) {
                        case 0: f = (float)log(av + 1e-6); break;
                        case 1: f = (v > 0.0) ? 1.0f : ((v < 0.0) ? -1.0f : 0.0f); break;
                        case 2: f = (av > 1e-6) ? (float)floor(log10(fmax(av, 1e-300))) : 0.0f; break;
                        case 3: f = (av == fl) ? 1.0f : 0.0f; break;
                        case 4: f = (v > 0.0) ? 1.0f : 0.0f; break;
                        case 5: f = (v == 0.0) ? 1.0f : 0.0f; break;
                        case 6: f = (v < 0.0) ? 1.0f : 0.0f; break;
                        case 7: {
                            bool pos_int = (v == floor(v)) && (v > 0.0);
                            double l2 = log2(fmax(v, 1.0));
                            f = (pos_int && (l2 == floor(l2))) ? 1.0f : 0.0f;
                        } break;
                        case 8: f = (fmt == 0) ? 1.0f : 0.0f; break;
                        case 9: f = (fmt == 1) ? 1.0f : 0.0f; break;
                    }
                }
                F[i] = f;
            }
        }
        __syncwarp();

        // ---- layer 1: [94] -> [256], exact GELU ----
        float* H = h_sm[warp];
        for (int j = 0; j < 8; j++) {
            const int col = j * 32 + lane;
            float acc = pb1[col];
            for (int k = 0; k < NUM_FEATS; k++)
                acc = fmaf(F[k], pw1[k * PROJ + col], acc);
            H[col] = 0.5f * acc * (1.0f + erff(acc * 0.70710678118654752f));
        }
        __syncwarp();

        // ---- layer 2: [256] -> [1024] ----
        float4 nacc[8];
        float sum = 0.f, sq = 0.f;
        for (int j = 0; j < 8; j++) {
            float4 acc = reinterpret_cast<const float4*>(pb2)[j * 32 + lane];
            for (int k = 0; k < PROJ; k++) {
                const float hk = H[k];
                const float4 wv =
                    reinterpret_cast<const float4*>(pw2 + (size_t)k * HIDDEN)[j * 32 + lane];
                acc.x = fmaf(hk, wv.x, acc.x);
                acc.y = fmaf(hk, wv.y, acc.y);
                acc.z = fmaf(hk, wv.z, acc.z);
                acc.w = fmaf(hk, wv.w, acc.w);
            }
            nacc[j] = acc;
            sum += acc.x + acc.y + acc.z + acc.w;
            sq  += acc.x * acc.x + acc.y * acc.y + acc.z * acc.z + acc.w * acc.w;
        }

        // ---- projection LayerNorm ----
        warp_red2(sum, sq);
        {
            const float mean = sum * (1.0f / 1024.0f);
            const float inv  = rsqrtf(sq * (1.0f / 1024.0f) - mean * mean + LN_EPS);
            for (int j = 0; j < 8; j++) {
                const float4 g = reinterpret_cast<const float4*>(pln_g)[j * 32 + lane];
                const float4 b = reinterpret_cast<const float4*>(pln_b)[j * 32 + lane];
                x[j].x += (nacc[j].x - mean) * inv * g.x + b.x;
                x[j].y += (nacc[j].y - mean) * inv * g.y + b.y;
                x[j].z += (nacc[j].z - mean) * inv * g.z + b.z;
                x[j].w += (nacc[j].w - mean) * inv * g.w + b.w;
            }
        }

        // ---- final LayerNorm ----
        sum = 0.f; sq = 0.f;
        #pragma unroll
        for (int j = 0; j < 8; j++) {
            sum += x[j].x + x[j].y + x[j].z + x[j].w;
            sq  += x[j].x * x[j].x + x[j].y * x[j].y + x[j].z * x[j].z + x[j].w * x[j].w;
        }
        warp_red2(sum, sq);
        const float mean = sum * (1.0f / 1024.0f);
        const float inv  = rsqrtf(sq * (1.0f / 1024.0f) - mean * mean + LN_EPS);

        float4* orow = reinterpret_cast<float4*>(out + (size_t)t * HIDDEN);
        #pragma unroll
        for (int j = 0; j < 8; j++) {
            const float4 g = reinterpret_cast<const float4*>(ln_g)[j * 32 + lane];
            const float4 b = reinterpret_cast<const float4*>(ln_b)[j * 32 + lane];
            float4 o;
            o.x = (x[j].x - mean) * inv * g.x + b.x;
            o.y = (x[j].y - mean) * inv * g.y + b.y;
            o.z = (x[j].z - mean) * inv * g.z + b.z;
            o.w = (x[j].w - mean) * inv * g.w + b.w;
            orow[j * 32 + lane] = o;
        }
        (void)val;
    }
}

extern "C" void kernel_launch(void* const* d_in, const int* in_sizes, int n_in,
                              void* d_out, int out_size)
{
    const int*   ids   = (const int*)  d_in[0];   // input_ids (int32 in harness)
    const float* vals  = (const float*)d_in[1];
    const int*   fmts  = (const int*)  d_in[2];
    const float* Wword = (const float*)d_in[3];   // [50257,1024]
    const float* Wpos  = (const float*)d_in[4];   // [4096,1024]
    const float* Wtype = (const float*)d_in[5];   // [2,1024]
    const float* ln_g  = (const float*)d_in[6];
    const float* ln_b  = (const float*)d_in[7];
    const float* pw1   = (const float*)d_in[8];   // [94,256]
    const float* pb1   = (const float*)d_in[9];
    const float* pw2   = (const float*)d_in[10];  // [256,1024]
    const float* pb2   = (const float*)d_in[11];
    const float* plng  = (const float*)d_in[12];
    const float* plnb  = (const float*)d_in[13];
    float*       out   = (float*)d_out;

    const int n_tokens = in_sizes[0];             // B*S = 16384

    const int grid_a = (n_tokens + WPB - 1) / WPB;
    embed_main_kernel<<<grid_a, THREADS_A>>>(
        ids, Wword, Wpos, Wtype, ln_g, ln_b, out, n_tokens);

    const int grid_b = (n_tokens + THREADS_B - 1) / THREADS_B;
    embed_fixup_kernel<<<grid_b, THREADS_B>>>(
        ids, vals, fmts, Wword, Wpos, Wtype, ln_g, ln_b,
        pw1, pb1, pw2, pb2, plng, plnb, out, n_tokens);
}